// round 8
// baseline (speedup 1.0000x reference)
#include <cuda_runtime.h>
#include <cstdint>

#define NN 100000
#define NE 800000
#define NBLK 148
#define ET 352          // edge kernel threads (11 warps)

typedef unsigned long long u64;
typedef unsigned int u32;

// scratch (allocation-free rule: __device__ globals)
__device__ float g_agg[NN * 32];
__device__ float g_P[NN * 64];          // fragment-major: [n][q*16 + nt*2 + c]
__device__ float g_Q[NN * 64];
__device__ ulonglong2 g_Ball[2048];     // edge weight frags (B0|B1|B2), bf16 hi|lo
__device__ ulonglong2 g_BP[2048];       // precompute weight frags (P|Q halves)

// ---------------- packed fp32x2 helpers ----------------
__device__ __forceinline__ u64 pack2(float x) {
    u64 r; asm("mov.b64 %0, {%1, %1};" : "=l"(r) : "f"(x)); return r;
}
__device__ __forceinline__ void ffma2(u64& d, u64 a, u64 b) {
    asm("fma.rn.f32x2 %0, %1, %2, %0;" : "+l"(d) : "l"(a), "l"(b));
}
__device__ __forceinline__ void rank1_16(float xf, const float* w16, u64* a0) {
    u64 xa = pack2(xf);
    const ulonglong2* wr = (const ulonglong2*)w16;
#pragma unroll
    for (int j = 0; j < 4; j++) {
        ulonglong2 w = wr[j];
        ffma2(a0[2 * j],     xa, w.x);
        ffma2(a0[2 * j + 1], xa, w.y);
    }
}

// ---------------- bf16 emulation helpers ----------------
__device__ __forceinline__ u32 bf2pack(float x0, float x1) {
    u32 r;
    asm("cvt.rn.bf16x2.f32 %0, %1, %2;" : "=r"(r) : "f"(x1), "f"(x0));
    return r;
}
__device__ __forceinline__ void split_bf2(float x0, float x1, u32& h, u32& l) {
    h = bf2pack(x0, x1);
    float r0 = x0 - __uint_as_float(h << 16);
    float r1 = x1 - __uint_as_float(h & 0xFFFF0000u);
    l = bf2pack(r0, r1);
}
__device__ __forceinline__ void mma_bf(float c[4], const u32 a[4], u32 b0, u32 b1) {
    asm volatile(
        "mma.sync.aligned.m16n8k16.row.col.f32.bf16.bf16.f32 "
        "{%0,%1,%2,%3}, {%4,%5,%6,%7}, {%8,%9}, {%0,%1,%2,%3};"
        : "+f"(c[0]), "+f"(c[1]), "+f"(c[2]), "+f"(c[3])
        : "r"(a[0]), "r"(a[1]), "r"(a[2]), "r"(a[3]), "r"(b0), "r"(b1));
}
// single-M-tile compensated K-chunk (pre_kernel)
template <int NTC>
__device__ __forceinline__ void gemm_step(float C[][4], const u32 ah[4], const u32 al[4],
                                          const ulonglong2* sB, int kc, int Kc, int lane) {
    u32 bh[NTC][2], bl[NTC][2];
#pragma unroll
    for (int nt = 0; nt < NTC; nt++) {
        ulonglong2 t = sB[(nt * Kc + kc) * 32 + lane];
        bh[nt][0] = (u32)t.x; bl[nt][0] = (u32)(t.x >> 32);
        bh[nt][1] = (u32)t.y; bl[nt][1] = (u32)(t.y >> 32);
    }
#pragma unroll
    for (int nt = 0; nt < NTC; nt++) mma_bf(C[nt], ah, bh[nt][0], bh[nt][1]);
#pragma unroll
    for (int nt = 0; nt < NTC; nt++) mma_bf(C[nt], ah, bl[nt][0], bl[nt][1]);
#pragma unroll
    for (int nt = 0; nt < NTC; nt++) mma_bf(C[nt], al, bh[nt][0], bh[nt][1]);
}
// dual-M-tile compensated K-chunk: B frags loaded once, feed both tiles
template <int NTC>
__device__ __forceinline__ void gemm_step2(float CA[][4], float CB[][4],
                                           const u32 aha[4], const u32 ala[4],
                                           const u32 ahb[4], const u32 alb[4],
                                           const ulonglong2* sB, int kc, int Kc, int lane) {
    u32 bh[NTC][2], bl[NTC][2];
#pragma unroll
    for (int nt = 0; nt < NTC; nt++) {
        ulonglong2 t = sB[(nt * Kc + kc) * 32 + lane];
        bh[nt][0] = (u32)t.x; bl[nt][0] = (u32)(t.x >> 32);
        bh[nt][1] = (u32)t.y; bl[nt][1] = (u32)(t.y >> 32);
    }
#pragma unroll
    for (int nt = 0; nt < NTC; nt++) {
        mma_bf(CA[nt], aha, bh[nt][0], bh[nt][1]);
        mma_bf(CB[nt], ahb, bh[nt][0], bh[nt][1]);
    }
#pragma unroll
    for (int nt = 0; nt < NTC; nt++) {
        mma_bf(CA[nt], aha, bl[nt][0], bl[nt][1]);
        mma_bf(CB[nt], ahb, bl[nt][0], bl[nt][1]);
    }
#pragma unroll
    for (int nt = 0; nt < NTC; nt++) {
        mma_bf(CA[nt], ala, bh[nt][0], bh[nt][1]);
        mma_bf(CB[nt], alb, bh[nt][0], bh[nt][1]);
    }
}
__device__ __forceinline__ void build_a(const float cA[4], const float cB[4],
                                        u32 ah[4], u32 al[4]) {
    split_bf2(fmaxf(cA[0], 0.f), fmaxf(cA[1], 0.f), ah[0], al[0]);
    split_bf2(fmaxf(cA[2], 0.f), fmaxf(cA[3], 0.f), ah[1], al[1]);
    split_bf2(fmaxf(cB[0], 0.f), fmaxf(cB[1], 0.f), ah[2], al[2]);
    split_bf2(fmaxf(cB[2], 0.f), fmaxf(cB[3], 0.f), ah[3], al[3]);
}
// no memory clobber: lets next-tile gathers pipeline past the scatter
__device__ __forceinline__ void red2(float* p, float x, float y) {
    asm volatile("red.global.add.v2.f32 [%0], {%1,%2};" :: "l"(p), "f"(x), "f"(y));
}

// ---------------- setup: natural-order bf16 hi|lo weight fragments ----------------
__global__ void setup_kernel(const float* __restrict__ w0, const float* __restrict__ w1,
                             const float* __restrict__ w2) {
    int i = blockIdx.x * 256 + threadIdx.x;
    if (i >= 4096) return;
    int lane = i & 31, f = i >> 5;
    int g = lane >> 2, q = lane & 3;
    float v00, v01, v10, v11;
    if (f < 64) {
        const float* W; int nidx, k0, stride;
        if (f < 16)      { int nt = f >> 1,  kc = f & 1;  W = w0 + 128 * 64; stride = 64; nidx = nt * 8 + g; k0 = 16 * kc + 2 * q; }
        else if (f < 48) { int ff = f - 16; int nt = ff >> 2, kc = ff & 3; W = w1; stride = 64; nidx = nt * 8 + g; k0 = 16 * kc + 2 * q; }
        else             { int ff = f - 48; int nt = ff >> 2, kc = ff & 3; W = w2; stride = 32; nidx = nt * 8 + g; k0 = 16 * kc + 2 * q; }
        v00 = W[(size_t)k0 * stride + nidx];
        v01 = W[(size_t)(k0 + 1) * stride + nidx];
        v10 = W[(size_t)(k0 + 8) * stride + nidx];
        v11 = W[(size_t)(k0 + 9) * stride + nidx];
    } else {
        int ff = f - 64;
        int nt = ff >> 2, kc = ff & 3;
        int isq = (nt >= 8) ? 32 : 0;
        int nidx = (nt & 7) * 8 + g;
        int k0 = 16 * kc + 2 * q;
        int r00 = ((k0     < 32) ? k0     : k0 + 32) + isq;
        int r01 = ((k0 + 1 < 32) ? k0 + 1 : k0 + 33) + isq;
        int r10 = ((k0 + 8 < 32) ? k0 + 8 : k0 + 40) + isq;
        int r11 = ((k0 + 9 < 32) ? k0 + 9 : k0 + 41) + isq;
        v00 = w0[(size_t)r00 * 64 + nidx];
        v01 = w0[(size_t)r01 * 64 + nidx];
        v10 = w0[(size_t)r10 * 64 + nidx];
        v11 = w0[(size_t)r11 * 64 + nidx];
    }
    u32 h0, l0, h1, l1;
    split_bf2(v00, v01, h0, l0);
    split_bf2(v10, v11, h1, l1);
    ulonglong2 t;
    t.x = (u64)h0 | ((u64)l0 << 32);
    t.y = (u64)h1 | ((u64)l1 << 32);
    if (f < 64) g_Ball[i] = t; else g_BP[i - 2048] = t;
}

// ---------------- precompute: P|Q = [h_s|h_d] @ W' via bf16 MMA; zeros g_agg ----------------
__global__ void __launch_bounds__(256, 1)
pre_kernel(const float* __restrict__ h_s, const float* __restrict__ h_d,
           const float* __restrict__ b0) {
    extern __shared__ ulonglong2 smem_v2[];
    float* s_b0 = (float*)(smem_v2 + 2048);
    const int tid = threadIdx.x, wid = tid >> 5, lane = tid & 31;
    const int g = lane >> 2, q = lane & 3;
    for (int i = tid; i < 2048; i += 256) smem_v2[i] = g_BP[i];
    if (tid < 64) s_b0[tid] = b0[tid];
    __syncthreads();

    int n0 = (blockIdx.x * 8 + wid) * 16;
    if (n0 >= NN) return;

    float C[16][4];
#pragma unroll
    for (int nt = 0; nt < 8; nt++) {
        C[nt][0] = 0.f; C[nt][1] = 0.f; C[nt][2] = 0.f; C[nt][3] = 0.f;
        float b0v = s_b0[nt * 8 + 2 * q], b1v = s_b0[nt * 8 + 2 * q + 1];
        C[8 + nt][0] = b0v; C[8 + nt][1] = b1v; C[8 + nt][2] = b0v; C[8 + nt][3] = b1v;
    }
#pragma unroll
    for (int kc = 0; kc < 4; kc++) {
        const float* src = (kc < 2) ? h_s : h_d;
        int off = (kc & 1) * 16 + 2 * q;
        float2 x0 = *(const float2*)(src + (size_t)(n0 + g) * 32 + off);
        float2 x1 = *(const float2*)(src + (size_t)(n0 + 8 + g) * 32 + off);
        float2 x2 = *(const float2*)(src + (size_t)(n0 + g) * 32 + off + 8);
        float2 x3 = *(const float2*)(src + (size_t)(n0 + 8 + g) * 32 + off + 8);
        u32 ah[4], al[4];
        split_bf2(x0.x, x0.y, ah[0], al[0]);
        split_bf2(x1.x, x1.y, ah[1], al[1]);
        split_bf2(x2.x, x2.y, ah[2], al[2]);
        split_bf2(x3.x, x3.y, ah[3], al[3]);
        gemm_step<8>(C,     ah, al, smem_v2,           kc, 4, lane);   // P
        gemm_step<8>(C + 8, ah, al, smem_v2 + 32 * 32, kc, 4, lane);   // Q
    }
#pragma unroll
    for (int j = 0; j < 4; j++) {
        *(float4*)(g_P + (size_t)(n0 + g)     * 64 + q * 16 + 4 * j) =
            make_float4(C[2*j][0], C[2*j][1], C[2*j+1][0], C[2*j+1][1]);
        *(float4*)(g_P + (size_t)(n0 + 8 + g) * 64 + q * 16 + 4 * j) =
            make_float4(C[2*j][2], C[2*j][3], C[2*j+1][2], C[2*j+1][3]);
        *(float4*)(g_Q + (size_t)(n0 + g)     * 64 + q * 16 + 4 * j) =
            make_float4(C[8+2*j][0], C[8+2*j][1], C[8+2*j+1][0], C[8+2*j+1][1]);
        *(float4*)(g_Q + (size_t)(n0 + 8 + g) * 64 + q * 16 + 4 * j) =
            make_float4(C[8+2*j][2], C[8+2*j][3], C[8+2*j+1][2], C[8+2*j+1][3]);
    }
    float4 z = make_float4(0.f, 0.f, 0.f, 0.f);
    float4* ag = (float4*)(g_agg + (size_t)n0 * 32);
#pragma unroll
    for (int i = 0; i < 4; i++) ag[lane + 32 * i] = z;
}

// ---------------- edge kernel: bf16 MMA MLP, 2 M-tiles (32 edges) per warp ----------------
#define SMEM_BYTES (2048 * 16 + 96 * 4)

__global__ void __launch_bounds__(ET, 1)
edge_kernel(const float* __restrict__ h_d, const float* __restrict__ ef,
            const int* __restrict__ si, const int* __restrict__ ri,
            const float* __restrict__ b1, const float* __restrict__ b2) {
    extern __shared__ ulonglong2 smem_v2[];
    ulonglong2* sB0 = smem_v2;           // 16 frags
    ulonglong2* sB1 = smem_v2 + 512;     // 32 frags
    ulonglong2* sB2 = smem_v2 + 1536;    // 16 frags
    float* s_b1 = (float*)(smem_v2 + 2048);
    float* s_b2 = s_b1 + 64;

    const int tid = threadIdx.x, wid = tid >> 5, lane = tid & 31;
    for (int i = tid; i < 2048; i += ET) smem_v2[i] = g_Ball[i];
    if (tid < 64) s_b1[tid] = b1[tid];
    if (tid < 32) s_b2[tid] = b2[tid];
    __syncthreads();

    const int g = lane >> 2, q = lane & 3;
    const int col2 = 2 * q;
    const int WPC = ET / 32;

#pragma unroll 1
    for (int base = blockIdx.x * (WPC * 32) + wid * 32; base < NE; base += NBLK * (WPC * 32)) {
        int e[4];
        bool v[4];
        int s[4], r[4];
#pragma unroll
        for (int t = 0; t < 4; t++) {
            int ee = base + 8 * t + g;
            v[t] = ee < NE;
            e[t] = v[t] ? ee : NE - 1;
            s[t] = si[e[t]];
            r[t] = ri[e[t]];
        }

        // ===== layer 0: C init from P[s]+Q[r], both M-tiles =====
        float CA[8][4], CB[8][4];
#pragma unroll
        for (int t = 0; t < 4; t++) {
            const float4* P = (const float4*)(g_P + (size_t)s[t] * 64 + q * 16);
            const float4* Q = (const float4*)(g_Q + (size_t)r[t] * 64 + q * 16);
            float (*C)[4] = (t < 2) ? CA : CB;
            int c01 = (t & 1) * 2;   // rows 0-7 -> c[0],c[1]; rows 8-15 -> c[2],c[3]
#pragma unroll
            for (int j = 0; j < 4; j++) {
                float4 p = P[j], qq = Q[j];
                C[2*j][c01]       = p.x + qq.x;
                C[2*j][c01 + 1]   = p.y + qq.y;
                C[2*j+1][c01]     = p.z + qq.z;
                C[2*j+1][c01 + 1] = p.w + qq.w;
            }
        }
        // ===== layer 0: += ef @ W0e =====
#pragma unroll
        for (int kc = 0; kc < 2; kc++) {
            int off = 16 * kc + col2;
            u32 aha[4], ala[4], ahb[4], alb[4];
#pragma unroll
            for (int t = 0; t < 4; t++) {
                float2 x0 = *(const float2*)(ef + (size_t)e[t] * 32 + off);
                float2 x1 = *(const float2*)(ef + (size_t)e[t] * 32 + off + 8);
                u32* ah = (t < 2) ? aha : ahb;
                u32* al = (t < 2) ? ala : alb;
                int b = (t & 1);
                split_bf2(x0.x, x0.y, ah[b],     al[b]);
                split_bf2(x1.x, x1.y, ah[b + 2], al[b + 2]);
            }
            gemm_step2<8>(CA, CB, aha, ala, ahb, alb, sB0, kc, 2, lane);
        }

        // ===== layer 1 =====
        float C1A[8][4], C1B[8][4];
#pragma unroll
        for (int nt = 0; nt < 8; nt++) {
            float bb0 = s_b1[nt * 8 + col2], bb1 = s_b1[nt * 8 + col2 + 1];
            C1A[nt][0] = bb0; C1A[nt][1] = bb1; C1A[nt][2] = bb0; C1A[nt][3] = bb1;
            C1B[nt][0] = bb0; C1B[nt][1] = bb1; C1B[nt][2] = bb0; C1B[nt][3] = bb1;
        }
#pragma unroll
        for (int kc = 0; kc < 4; kc++) {
            u32 aha[4], ala[4], ahb[4], alb[4];
            build_a(CA[2 * kc], CA[2 * kc + 1], aha, ala);
            build_a(CB[2 * kc], CB[2 * kc + 1], ahb, alb);
            gemm_step2<8>(C1A, C1B, aha, ala, ahb, alb, sB1, kc, 4, lane);
        }

        // ===== layer 2 =====
        float C2A[4][4], C2B[4][4];
#pragma unroll
        for (int nt = 0; nt < 4; nt++) {
            float bb0 = s_b2[nt * 8 + col2], bb1 = s_b2[nt * 8 + col2 + 1];
            C2A[nt][0] = bb0; C2A[nt][1] = bb1; C2A[nt][2] = bb0; C2A[nt][3] = bb1;
            C2B[nt][0] = bb0; C2B[nt][1] = bb1; C2B[nt][2] = bb0; C2B[nt][3] = bb1;
        }
#pragma unroll
        for (int kc = 0; kc < 4; kc++) {
            u32 aha[4], ala[4], ahb[4], alb[4];
            build_a(C1A[2 * kc], C1A[2 * kc + 1], aha, ala);
            build_a(C1B[2 * kc], C1B[2 * kc + 1], ahb, alb);
            gemm_step2<4>(C2A, C2B, aha, ala, ahb, alb, sB2, kc, 4, lane);
        }

        // ===== epilogue: relu(psi) * (h_dj - h_di), scatter-add, both tiles =====
#pragma unroll
        for (int t = 0; t < 4; t++) {
            if (!v[t]) continue;
            float (*C2)[4] = (t < 2) ? C2A : C2B;
            int c01 = (t & 1) * 2;
            const float* dj = h_d + (size_t)r[t] * 32;
            const float* di = h_d + (size_t)s[t] * 32;
#pragma unroll
            for (int nt = 0; nt < 4; nt++) {
                int cc = nt * 8 + col2;
                float2 a = *(const float2*)(dj + cc);
                float2 b = *(const float2*)(di + cc);
                red2(g_agg + (size_t)r[t] * 32 + cc,
                     fmaxf(C2[nt][c01], 0.f)     * (a.x - b.x),
                     fmaxf(C2[nt][c01 + 1], 0.f) * (a.y - b.y));
            }
        }
    }
}

// out[n] = h_d_prev[n] + agg[n] @ W   (2 threads per node, 16 outputs each)
__global__ void __launch_bounds__(256)
final_kernel(const float* __restrict__ h_d, const float* __restrict__ W,
             float* __restrict__ out) {
    __shared__ float sW[1024];
    int tid = threadIdx.x;
    {
        float4* d4 = (float4*)sW;
        const float4* s4 = (const float4*)W;
        for (int i = tid; i < 256; i += 256) d4[i] = s4[i];
    }
    __syncthreads();
    int idx = blockIdx.x * 256 + tid;
    int n = idx >> 1, half = idx & 1;
    if (n >= NN) return;

    u64 acc[8];
    {
        const ulonglong2* hp = (const ulonglong2*)(h_d + (size_t)n * 32 + half * 16);
#pragma unroll
        for (int j = 0; j < 4; j++) {
            ulonglong2 t = hp[j];
            acc[2 * j] = t.x; acc[2 * j + 1] = t.y;
        }
    }
    const float4* ap = (const float4*)(g_agg + (size_t)n * 32);
    const float* wb = sW + half * 16;
#pragma unroll
    for (int i = 0; i < 8; i++) {
        float4 a = ap[i];
        rank1_16(a.x, wb + (4 * i) * 32,     acc);
        rank1_16(a.y, wb + (4 * i + 1) * 32, acc);
        rank1_16(a.z, wb + (4 * i + 2) * 32, acc);
        rank1_16(a.w, wb + (4 * i + 3) * 32, acc);
    }
    ulonglong2* op = (ulonglong2*)(out + (size_t)n * 32 + half * 16);
#pragma unroll
    for (int j = 0; j < 4; j++) {
        ulonglong2 t; t.x = acc[2 * j]; t.y = acc[2 * j + 1];
        op[j] = t;
    }
}

extern "C" void kernel_launch(void* const* d_in, const int* in_sizes, int n_in,
                              void* d_out, int out_size) {
    const float* h_d = (const float*)d_in[0];
    const float* h_s = (const float*)d_in[1];
    const float* ef  = (const float*)d_in[2];
    const int*   si  = (const int*)d_in[3];
    const int*   ri  = (const int*)d_in[4];
    const float* w0  = (const float*)d_in[5];
    const float* b0  = (const float*)d_in[6];
    const float* w1  = (const float*)d_in[7];
    const float* b1  = (const float*)d_in[8];
    const float* w2  = (const float*)d_in[9];
    const float* b2  = (const float*)d_in[10];
    const float* W   = (const float*)d_in[11];
    float* out = (float*)d_out;

    cudaFuncSetAttribute(edge_kernel, cudaFuncAttributeMaxDynamicSharedMemorySize,
                         SMEM_BYTES);
    cudaFuncSetAttribute(pre_kernel, cudaFuncAttributeMaxDynamicSharedMemorySize,
                         2048 * 16 + 64 * 4);

    setup_kernel<<<16, 256>>>(w0, w1, w2);
    pre_kernel<<<782, 256, 2048 * 16 + 64 * 4>>>(h_s, h_d, b0);
    edge_kernel<<<NBLK, ET, SMEM_BYTES>>>(h_d, ef, si, ri, b1, b2);
    final_kernel<<<(2 * NN + 255) / 256, 256>>>(h_d, W, out);
}

// round 9
// speedup vs baseline: 1.0310x; 1.0310x over previous
#include <cuda_runtime.h>
#include <cstdint>

#define NN 100000
#define NE 800000
#define NBLK 148
#define ET 448          // edge kernel threads (14 warps)

typedef unsigned long long u64;
typedef unsigned int u32;

// scratch (allocation-free rule: __device__ globals)
__device__ float g_agg[NN * 32];
__device__ float g_P[NN * 64];          // fragment-major: [n][q*16 + nt*2 + c]
__device__ float g_Q[NN * 64];
__device__ ulonglong2 g_Ball[2048];     // edge weight frags (B0|B1|B2), bf16 hi|lo
__device__ ulonglong2 g_BP[2048];       // precompute weight frags (P|Q halves)

// ---------------- packed fp32x2 helpers ----------------
__device__ __forceinline__ u64 pack2(float x) {
    u64 r; asm("mov.b64 %0, {%1, %1};" : "=l"(r) : "f"(x)); return r;
}
__device__ __forceinline__ void ffma2(u64& d, u64 a, u64 b) {
    asm("fma.rn.f32x2 %0, %1, %2, %0;" : "+l"(d) : "l"(a), "l"(b));
}
__device__ __forceinline__ void rank1_16(float xf, const float* w16, u64* a0) {
    u64 xa = pack2(xf);
    const ulonglong2* wr = (const ulonglong2*)w16;
#pragma unroll
    for (int j = 0; j < 4; j++) {
        ulonglong2 w = wr[j];
        ffma2(a0[2 * j],     xa, w.x);
        ffma2(a0[2 * j + 1], xa, w.y);
    }
}

// ---------------- bf16 emulation helpers ----------------
__device__ __forceinline__ u32 bf2pack(float x0, float x1) {
    u32 r;
    asm("cvt.rn.bf16x2.f32 %0, %1, %2;" : "=r"(r) : "f"(x1), "f"(x0));
    return r;
}
__device__ __forceinline__ void split_bf2(float x0, float x1, u32& h, u32& l) {
    h = bf2pack(x0, x1);
    float r0 = x0 - __uint_as_float(h << 16);
    float r1 = x1 - __uint_as_float(h & 0xFFFF0000u);
    l = bf2pack(r0, r1);
}
__device__ __forceinline__ void mma_bf(float c[4], const u32 a[4], u32 b0, u32 b1) {
    asm volatile(
        "mma.sync.aligned.m16n8k16.row.col.f32.bf16.bf16.f32 "
        "{%0,%1,%2,%3}, {%4,%5,%6,%7}, {%8,%9}, {%0,%1,%2,%3};"
        : "+f"(c[0]), "+f"(c[1]), "+f"(c[2]), "+f"(c[3])
        : "r"(a[0]), "r"(a[1]), "r"(a[2]), "r"(a[3]), "r"(b0), "r"(b1));
}
template <int NTC>
__device__ __forceinline__ void gemm_step(float C[][4], const u32 ah[4], const u32 al[4],
                                          const ulonglong2* sB, int kc, int Kc, int lane) {
    u32 bh[NTC][2], bl[NTC][2];
#pragma unroll
    for (int nt = 0; nt < NTC; nt++) {
        ulonglong2 t = sB[(nt * Kc + kc) * 32 + lane];
        bh[nt][0] = (u32)t.x; bl[nt][0] = (u32)(t.x >> 32);
        bh[nt][1] = (u32)t.y; bl[nt][1] = (u32)(t.y >> 32);
    }
#pragma unroll
    for (int nt = 0; nt < NTC; nt++) mma_bf(C[nt], ah, bh[nt][0], bh[nt][1]);
#pragma unroll
    for (int nt = 0; nt < NTC; nt++) mma_bf(C[nt], ah, bl[nt][0], bl[nt][1]);
#pragma unroll
    for (int nt = 0; nt < NTC; nt++) mma_bf(C[nt], al, bh[nt][0], bh[nt][1]);
}
__device__ __forceinline__ void build_a(const float cA[4], const float cB[4],
                                        u32 ah[4], u32 al[4]) {
    split_bf2(fmaxf(cA[0], 0.f), fmaxf(cA[1], 0.f), ah[0], al[0]);
    split_bf2(fmaxf(cA[2], 0.f), fmaxf(cA[3], 0.f), ah[1], al[1]);
    split_bf2(fmaxf(cB[0], 0.f), fmaxf(cB[1], 0.f), ah[2], al[2]);
    split_bf2(fmaxf(cB[2], 0.f), fmaxf(cB[3], 0.f), ah[3], al[3]);
}
// no memory clobber: lets next-tile gathers pipeline past the scatter
__device__ __forceinline__ void red2(float* p, float x, float y) {
    asm volatile("red.global.add.v2.f32 [%0], {%1,%2};" :: "l"(p), "f"(x), "f"(y));
}

// ---------------- setup: natural-order bf16 hi|lo weight fragments ----------------
__global__ void setup_kernel(const float* __restrict__ w0, const float* __restrict__ w1,
                             const float* __restrict__ w2) {
    int i = blockIdx.x * 256 + threadIdx.x;
    if (i >= 4096) return;
    int lane = i & 31, f = i >> 5;
    int g = lane >> 2, q = lane & 3;
    float v00, v01, v10, v11;
    if (f < 64) {
        const float* W; int nidx, k0, stride;
        if (f < 16)      { int nt = f >> 1,  kc = f & 1;  W = w0 + 128 * 64; stride = 64; nidx = nt * 8 + g; k0 = 16 * kc + 2 * q; }
        else if (f < 48) { int ff = f - 16; int nt = ff >> 2, kc = ff & 3; W = w1; stride = 64; nidx = nt * 8 + g; k0 = 16 * kc + 2 * q; }
        else             { int ff = f - 48; int nt = ff >> 2, kc = ff & 3; W = w2; stride = 32; nidx = nt * 8 + g; k0 = 16 * kc + 2 * q; }
        v00 = W[(size_t)k0 * stride + nidx];
        v01 = W[(size_t)(k0 + 1) * stride + nidx];
        v10 = W[(size_t)(k0 + 8) * stride + nidx];
        v11 = W[(size_t)(k0 + 9) * stride + nidx];
    } else {
        int ff = f - 64;
        int nt = ff >> 2, kc = ff & 3;
        int isq = (nt >= 8) ? 32 : 0;
        int nidx = (nt & 7) * 8 + g;
        int k0 = 16 * kc + 2 * q;
        int r00 = ((k0     < 32) ? k0     : k0 + 32) + isq;
        int r01 = ((k0 + 1 < 32) ? k0 + 1 : k0 + 33) + isq;
        int r10 = ((k0 + 8 < 32) ? k0 + 8 : k0 + 40) + isq;
        int r11 = ((k0 + 9 < 32) ? k0 + 9 : k0 + 41) + isq;
        v00 = w0[(size_t)r00 * 64 + nidx];
        v01 = w0[(size_t)r01 * 64 + nidx];
        v10 = w0[(size_t)r10 * 64 + nidx];
        v11 = w0[(size_t)r11 * 64 + nidx];
    }
    u32 h0, l0, h1, l1;
    split_bf2(v00, v01, h0, l0);
    split_bf2(v10, v11, h1, l1);
    ulonglong2 t;
    t.x = (u64)h0 | ((u64)l0 << 32);
    t.y = (u64)h1 | ((u64)l1 << 32);
    if (f < 64) g_Ball[i] = t; else g_BP[i - 2048] = t;
}

// ---------------- precompute: P|Q = [h_s|h_d] @ W' via bf16 MMA; zeros g_agg ----------------
__global__ void __launch_bounds__(256, 1)
pre_kernel(const float* __restrict__ h_s, const float* __restrict__ h_d,
           const float* __restrict__ b0) {
    extern __shared__ ulonglong2 smem_v2[];
    float* s_b0 = (float*)(smem_v2 + 2048);
    const int tid = threadIdx.x, wid = tid >> 5, lane = tid & 31;
    const int g = lane >> 2, q = lane & 3;
    for (int i = tid; i < 2048; i += 256) smem_v2[i] = g_BP[i];
    if (tid < 64) s_b0[tid] = b0[tid];
    __syncthreads();

    int n0 = (blockIdx.x * 8 + wid) * 16;
    if (n0 >= NN) return;

    float C[16][4];
#pragma unroll
    for (int nt = 0; nt < 8; nt++) {
        C[nt][0] = 0.f; C[nt][1] = 0.f; C[nt][2] = 0.f; C[nt][3] = 0.f;
        float b0v = s_b0[nt * 8 + 2 * q], b1v = s_b0[nt * 8 + 2 * q + 1];
        C[8 + nt][0] = b0v; C[8 + nt][1] = b1v; C[8 + nt][2] = b0v; C[8 + nt][3] = b1v;
    }
#pragma unroll
    for (int kc = 0; kc < 4; kc++) {
        const float* src = (kc < 2) ? h_s : h_d;
        int off = (kc & 1) * 16 + 2 * q;
        float2 x0 = *(const float2*)(src + (size_t)(n0 + g) * 32 + off);
        float2 x1 = *(const float2*)(src + (size_t)(n0 + 8 + g) * 32 + off);
        float2 x2 = *(const float2*)(src + (size_t)(n0 + g) * 32 + off + 8);
        float2 x3 = *(const float2*)(src + (size_t)(n0 + 8 + g) * 32 + off + 8);
        u32 ah[4], al[4];
        split_bf2(x0.x, x0.y, ah[0], al[0]);
        split_bf2(x1.x, x1.y, ah[1], al[1]);
        split_bf2(x2.x, x2.y, ah[2], al[2]);
        split_bf2(x3.x, x3.y, ah[3], al[3]);
        gemm_step<8>(C,     ah, al, smem_v2,           kc, 4, lane);   // P
        gemm_step<8>(C + 8, ah, al, smem_v2 + 32 * 32, kc, 4, lane);   // Q
    }
#pragma unroll
    for (int j = 0; j < 4; j++) {
        *(float4*)(g_P + (size_t)(n0 + g)     * 64 + q * 16 + 4 * j) =
            make_float4(C[2*j][0], C[2*j][1], C[2*j+1][0], C[2*j+1][1]);
        *(float4*)(g_P + (size_t)(n0 + 8 + g) * 64 + q * 16 + 4 * j) =
            make_float4(C[2*j][2], C[2*j][3], C[2*j+1][2], C[2*j+1][3]);
        *(float4*)(g_Q + (size_t)(n0 + g)     * 64 + q * 16 + 4 * j) =
            make_float4(C[8+2*j][0], C[8+2*j][1], C[8+2*j+1][0], C[8+2*j+1][1]);
        *(float4*)(g_Q + (size_t)(n0 + 8 + g) * 64 + q * 16 + 4 * j) =
            make_float4(C[8+2*j][2], C[8+2*j][3], C[8+2*j+1][2], C[8+2*j+1][3]);
    }
    float4 z = make_float4(0.f, 0.f, 0.f, 0.f);
    float4* ag = (float4*)(g_agg + (size_t)n0 * 32);
#pragma unroll
    for (int i = 0; i < 4; i++) ag[lane + 32 * i] = z;
}

// ---------------- edge kernel: bf16 MMA MLP, index-prefetched ----------------
#define SMEM_BYTES (2048 * 16 + 96 * 4)

__global__ void __launch_bounds__(ET, 1)
edge_kernel(const float* __restrict__ h_d, const float* __restrict__ ef,
            const int* __restrict__ si, const int* __restrict__ ri,
            const float* __restrict__ b1, const float* __restrict__ b2) {
    extern __shared__ ulonglong2 smem_v2[];
    ulonglong2* sB0 = smem_v2;           // 16 frags
    ulonglong2* sB1 = smem_v2 + 512;     // 32 frags
    ulonglong2* sB2 = smem_v2 + 1536;    // 16 frags
    float* s_b1 = (float*)(smem_v2 + 2048);
    float* s_b2 = s_b1 + 64;

    const int tid = threadIdx.x, wid = tid >> 5, lane = tid & 31;
    for (int i = tid; i < 2048; i += ET) smem_v2[i] = g_Ball[i];
    if (tid < 64) s_b1[tid] = b1[tid];
    if (tid < 32) s_b2[tid] = b2[tid];
    __syncthreads();

    const int g = lane >> 2, q = lane & 3;
    const int col2 = 2 * q;
    const int WPC = ET / 32;
    const int STEP = NBLK * (WPC * 16);

    int base = blockIdx.x * (WPC * 16) + wid * 16;
    if (base >= NE) return;

    // prime the index pipeline for the first tile
    int e0 = base + g, e1 = base + 8 + g;
    bool v0 = e0 < NE, v1 = e1 < NE;
    int e0c = v0 ? e0 : NE - 1;
    int e1c = v1 ? e1 : NE - 1;
    int s0 = si[e0c], rc0 = ri[e0c];
    int s1 = si[e1c], rc1 = ri[e1c];

#pragma unroll 1
    for (; base < NE; base += STEP) {
        // ---- prefetch next tile's indices (first L2 hop off the critical path) ----
        int nbase = base + STEP;
        int ne0 = nbase + g, ne1 = nbase + 8 + g;
        int ne0c = (ne0 < NE) ? ne0 : NE - 1;
        int ne1c = (ne1 < NE) ? ne1 : NE - 1;
        int ns0 = si[ne0c], nrc0 = ri[ne0c];
        int ns1 = si[ne1c], nrc1 = ri[ne1c];

        // ===== layer 0: C init from P[s]+Q[r] =====
        float C[8][4];
        {
            const float4* P0 = (const float4*)(g_P + (size_t)s0  * 64 + q * 16);
            const float4* Q0 = (const float4*)(g_Q + (size_t)rc0 * 64 + q * 16);
            const float4* P1 = (const float4*)(g_P + (size_t)s1  * 64 + q * 16);
            const float4* Q1 = (const float4*)(g_Q + (size_t)rc1 * 64 + q * 16);
#pragma unroll
            for (int j = 0; j < 4; j++) {
                float4 p = P0[j], qq = Q0[j];
                C[2*j][0]   = p.x + qq.x; C[2*j][1]   = p.y + qq.y;
                C[2*j+1][0] = p.z + qq.z; C[2*j+1][1] = p.w + qq.w;
                p = P1[j]; qq = Q1[j];
                C[2*j][2]   = p.x + qq.x; C[2*j][3]   = p.y + qq.y;
                C[2*j+1][2] = p.z + qq.z; C[2*j+1][3] = p.w + qq.w;
            }
        }
        // ===== layer 0: += ef @ W0e =====
#pragma unroll
        for (int kc = 0; kc < 2; kc++) {
            int off = 16 * kc + col2;
            float2 x0 = *(const float2*)(ef + (size_t)e0c * 32 + off);
            float2 x1 = *(const float2*)(ef + (size_t)e1c * 32 + off);
            float2 x2 = *(const float2*)(ef + (size_t)e0c * 32 + off + 8);
            float2 x3 = *(const float2*)(ef + (size_t)e1c * 32 + off + 8);
            u32 ah[4], al[4];
            split_bf2(x0.x, x0.y, ah[0], al[0]);
            split_bf2(x1.x, x1.y, ah[1], al[1]);
            split_bf2(x2.x, x2.y, ah[2], al[2]);
            split_bf2(x3.x, x3.y, ah[3], al[3]);
            gemm_step<8>(C, ah, al, sB0, kc, 2, lane);
        }

        // ===== layer 1 =====
        float C1[8][4];
#pragma unroll
        for (int nt = 0; nt < 8; nt++) {
            float bb0 = s_b1[nt * 8 + col2], bb1 = s_b1[nt * 8 + col2 + 1];
            C1[nt][0] = bb0; C1[nt][1] = bb1; C1[nt][2] = bb0; C1[nt][3] = bb1;
        }
#pragma unroll
        for (int kc = 0; kc < 4; kc++) {
            u32 ah[4], al[4];
            build_a(C[2 * kc], C[2 * kc + 1], ah, al);
            gemm_step<8>(C1, ah, al, sB1, kc, 4, lane);
        }

        // ===== layer 2 =====
        float C2[4][4];
#pragma unroll
        for (int nt = 0; nt < 4; nt++) {
            float bb0 = s_b2[nt * 8 + col2], bb1 = s_b2[nt * 8 + col2 + 1];
            C2[nt][0] = bb0; C2[nt][1] = bb1; C2[nt][2] = bb0; C2[nt][3] = bb1;
        }
#pragma unroll
        for (int kc = 0; kc < 4; kc++) {
            u32 ah[4], al[4];
            build_a(C1[2 * kc], C1[2 * kc + 1], ah, al);
            gemm_step<4>(C2, ah, al, sB2, kc, 4, lane);
        }

        // ===== epilogue: relu(psi) * (h_dj - h_di), vector scatter-add =====
#pragma unroll
        for (int nt = 0; nt < 4; nt++) {
            int cc = nt * 8 + col2;
            if (v0) {
                float2 dj = *(const float2*)(h_d + (size_t)rc0 * 32 + cc);
                float2 di = *(const float2*)(h_d + (size_t)s0 * 32 + cc);
                red2(g_agg + (size_t)rc0 * 32 + cc,
                     fmaxf(C2[nt][0], 0.f) * (dj.x - di.x),
                     fmaxf(C2[nt][1], 0.f) * (dj.y - di.y));
            }
            if (v1) {
                float2 dj = *(const float2*)(h_d + (size_t)rc1 * 32 + cc);
                float2 di = *(const float2*)(h_d + (size_t)s1 * 32 + cc);
                red2(g_agg + (size_t)rc1 * 32 + cc,
                     fmaxf(C2[nt][2], 0.f) * (dj.x - di.x),
                     fmaxf(C2[nt][3], 0.f) * (dj.y - di.y));
            }
        }

        // rotate prefetched indices into place
        e0c = ne0c; e1c = ne1c;
        v0 = ne0 < NE; v1 = ne1 < NE;
        s0 = ns0; rc0 = nrc0; s1 = ns1; rc1 = nrc1;
    }
}

// out[n] = h_d_prev[n] + agg[n] @ W   (2 threads per node, 16 outputs each)
__global__ void __launch_bounds__(256)
final_kernel(const float* __restrict__ h_d, const float* __restrict__ W,
             float* __restrict__ out) {
    __shared__ float sW[1024];
    int tid = threadIdx.x;
    {
        float4* d4 = (float4*)sW;
        const float4* s4 = (const float4*)W;
        for (int i = tid; i < 256; i += 256) d4[i] = s4[i];
    }
    __syncthreads();
    int idx = blockIdx.x * 256 + tid;
    int n = idx >> 1, half = idx & 1;
    if (n >= NN) return;

    u64 acc[8];
    {
        const ulonglong2* hp = (const ulonglong2*)(h_d + (size_t)n * 32 + half * 16);
#pragma unroll
        for (int j = 0; j < 4; j++) {
            ulonglong2 t = hp[j];
            acc[2 * j] = t.x; acc[2 * j + 1] = t.y;
        }
    }
    const float4* ap = (const float4*)(g_agg + (size_t)n * 32);
    const float* wb = sW + half * 16;
#pragma unroll
    for (int i = 0; i < 8; i++) {
        float4 a = ap[i];
        rank1_16(a.x, wb + (4 * i) * 32,     acc);
        rank1_16(a.y, wb + (4 * i + 1) * 32, acc);
        rank1_16(a.z, wb + (4 * i + 2) * 32, acc);
        rank1_16(a.w, wb + (4 * i + 3) * 32, acc);
    }
    ulonglong2* op = (ulonglong2*)(out + (size_t)n * 32 + half * 16);
#pragma unroll
    for (int j = 0; j < 4; j++) {
        ulonglong2 t; t.x = acc[2 * j]; t.y = acc[2 * j + 1];
        op[j] = t;
    }
}

extern "C" void kernel_launch(void* const* d_in, const int* in_sizes, int n_in,
                              void* d_out, int out_size) {
    const float* h_d = (const float*)d_in[0];
    const float* h_s = (const float*)d_in[1];
    const float* ef  = (const float*)d_in[2];
    const int*   si  = (const int*)d_in[3];
    const int*   ri  = (const int*)d_in[4];
    const float* w0  = (const float*)d_in[5];
    const float* b0  = (const float*)d_in[6];
    const float* w1  = (const float*)d_in[7];
    const float* b1  = (const float*)d_in[8];
    const float* w2  = (const float*)d_in[9];
    const float* b2  = (const float*)d_in[10];
    const float* W   = (const float*)d_in[11];
    float* out = (float*)d_out;

    cudaFuncSetAttribute(edge_kernel, cudaFuncAttributeMaxDynamicSharedMemorySize,
                         SMEM_BYTES);
    cudaFuncSetAttribute(pre_kernel, cudaFuncAttributeMaxDynamicSharedMemorySize,
                         2048 * 16 + 64 * 4);

    setup_kernel<<<16, 256>>>(w0, w1, w2);
    pre_kernel<<<782, 256, 2048 * 16 + 64 * 4>>>(h_s, h_d, b0);
    edge_kernel<<<NBLK, ET, SMEM_BYTES>>>(h_d, ef, si, ri, b1, b2);
    final_kernel<<<(2 * NN + 255) / 256, 256>>>(h_d, W, out);
}